// round 11
// baseline (speedup 1.0000x reference)
#include <cuda_runtime.h>
#include <cuda_bf16.h>
#include <cstdint>

#define TOK_TOTAL 32768
#define NCTA 512                  // 64 tokens per CTA (2 pairs x 32)

extern __shared__ __align__(128) uint8_t smbuf[];

// fp16 B panels, v4-packed (layout unchanged from R8/R9)
__device__ __align__(16) uint8_t g_BpkH[65 * 8192];
__device__ __align__(16) uint8_t g_W3pkH[8192];
__device__ __align__(16) uint8_t g_W11pk[32768];
__device__ __align__(16) uint8_t g_W21pk[32768];
__device__ __align__(16) uint8_t g_W12pk[16384];

// ---------------------------------------------------------------------------
__device__ __forceinline__ void split_pair(float v0, float v1, uint32_t& h, uint32_t& l) {
    asm("cvt.rn.bf16x2.f32 %0, %1, %2;" : "=r"(h) : "f"(v1), "f"(v0));
    float h0 = __uint_as_float(h << 16);
    float h1 = __uint_as_float(h & 0xffff0000u);
    asm("cvt.rn.bf16x2.f32 %0, %1, %2;" : "=r"(l) : "f"(v1 - h1), "f"(v0 - h0));
}
__device__ __forceinline__ uint32_t f16x2(float v0, float v1) {
    uint32_t r;
    asm("cvt.rn.f16x2.f32 %0, %1, %2;" : "=r"(r) : "f"(v1), "f"(v0));
    return r;
}
__device__ __forceinline__ uint32_t hmul2(uint32_t a, uint32_t b) {
    uint32_t r;
    asm("mul.rn.f16x2 %0, %1, %2;" : "=r"(r) : "r"(a), "r"(b));
    return r;
}

#define MMA_BF16(Cq, A, b0, b1)                                              \
    asm volatile("mma.sync.aligned.m16n8k16.row.col.f32.bf16.bf16.f32 "      \
                 "{%0,%1,%2,%3}, {%4,%5,%6,%7}, {%8,%9}, {%0,%1,%2,%3};"     \
                 : "+f"((Cq)[0]), "+f"((Cq)[1]), "+f"((Cq)[2]), "+f"((Cq)[3])\
                 : "r"((A)[0]), "r"((A)[1]), "r"((A)[2]), "r"((A)[3]),       \
                   "r"(b0), "r"(b1))

#define MMA_F16(Cq, A, b0, b1)                                               \
    asm volatile("mma.sync.aligned.m16n8k16.row.col.f32.f16.f16.f32 "        \
                 "{%0,%1,%2,%3}, {%4,%5,%6,%7}, {%8,%9}, {%0,%1,%2,%3};"     \
                 : "+f"((Cq)[0]), "+f"((Cq)[1]), "+f"((Cq)[2]), "+f"((Cq)[3])\
                 : "r"((A)[0]), "r"((A)[1]), "r"((A)[2]), "r"((A)[3]),       \
                   "r"(b0), "r"(b1))

// ---------------------------------------------------------------------------
// Convert (unchanged)
// ---------------------------------------------------------------------------
__device__ __forceinline__ void pack_frag_bf(const float* src, uint8_t* dst,
                                             int kc, int nt, int l, int loOff) {
    int q2 = (l & 3) * 2;
    int o  = nt * 8 + (l >> 2);
    int i0 = kc * 16 + q2;
    float v0 = src[(i0    ) * 64 + o];
    float v1 = src[(i0 + 1) * 64 + o];
    float v2 = src[(i0 + 8) * 64 + o];
    float v3 = src[(i0 + 9) * 64 + o];
    uint32_t h0, l0, h1, l1;
    split_pair(v0, v1, h0, l0);
    split_pair(v2, v3, h1, l1);
    uint8_t* d = dst + (kc * 8 + nt) * 256 + l * 8;
    *(uint32_t*)(d)             = h0;
    *(uint32_t*)(d + 4)         = h1;
    *(uint32_t*)(d + loOff)     = l0;
    *(uint32_t*)(d + loOff + 4) = l1;
}
__device__ __forceinline__ void pack_frag_h4(const float* src, uint8_t* dst,
                                             int kc, int np, int l) {
    int q2 = (l & 3) * 2;
    int i0 = kc * 16 + q2;
    uint32_t r[4];
    #pragma unroll
    for (int h = 0; h < 2; h++) {
        int o = (2 * np + h) * 8 + (l >> 2);
        r[h*2+0] = f16x2(src[(i0    ) * 64 + o], src[(i0 + 1) * 64 + o]);
        r[h*2+1] = f16x2(src[(i0 + 8) * 64 + o], src[(i0 + 9) * 64 + o]);
    }
    *(uint4*)(dst + (kc * 4 + np) * 512 + l * 16) = make_uint4(r[0], r[1], r[2], r[3]);
}

__global__ __launch_bounds__(256) void convert_kernel(
    const float* __restrict__ W22, const float* __restrict__ b22,
    const float* __restrict__ W3,  const float* __restrict__ W11,
    const float* __restrict__ W21, const float* __restrict__ W12)
{
    int gid = blockIdx.x * 256 + threadIdx.x;
    if (gid < 33280) {
        int j = gid >> 9;
        int r = gid & 511;
        const float* src = (j < 64) ? (W22 + j * 4096) : b22;
        pack_frag_h4(src, g_BpkH + j * 8192, r >> 7, (r >> 5) & 3, r & 31);
    } else if (gid < 33792) {
        int r = gid - 33280;
        pack_frag_h4(W3, g_W3pkH, r >> 7, (r >> 5) & 3, r & 31);
    } else if (gid < 35840) {
        int r = gid - 33792;
        pack_frag_bf(W11, g_W11pk, r >> 8, (r >> 5) & 7, r & 31, 16384);
    } else if (gid < 37888) {
        int r = gid - 35840;
        pack_frag_bf(W21, g_W21pk, r >> 8, (r >> 5) & 7, r & 31, 16384);
    } else if (gid < 38912) {
        int r = gid - 37888;
        pack_frag_bf(W12, g_W12pk, r >> 8, (r >> 5) & 7, r & 31, 8192);
    }
}

// ---------------------------------------------------------------------------
// Fused kernel, split-K over j:
//   CTA = 128 thr = 4 warps = 2 pairs; pair owns 32 tokens.
//   role 0: phase1 C1->W12f (shares w12 frags via smem); main loop j=0..31.
//   role 1: phase1 C2->w21 (shares transposed rows);     main loop j=32..64.
//   Combine partial C via smem; each warp does LN+W3+store for one 16-tok tile.
// smem: w21s 2x9216 @0 | w12ps 2x4096 @18432 | Cs 4x4096 @26624 ; total 43008
// ---------------------------------------------------------------------------
#define S_SZ 43008u

__device__ __forceinline__ float2 catld(const float* __restrict__ img,
                                        const float* __restrict__ loc,
                                        int row, int c) {
    if (c < 64) return *(const float2*)&img[row * 64 + c];
    return *(const float2*)&loc[row * 64 + c - 64];
}

__global__ __launch_bounds__(128, 3) void fused_kernel(
    const float* __restrict__ img, const float* __restrict__ loc,
    const float* __restrict__ b11, const float* __restrict__ b21,
    const float* __restrict__ b12, const float* __restrict__ lnG,
    const float* __restrict__ lnB, const float* __restrict__ b3,
    float* __restrict__ out)
{
    const int tid  = threadIdx.x;
    const int l    = tid & 31;
    const int w    = tid >> 5;
    const int pid  = w >> 1;
    const int role = w & 1;
    const int pairBase = blockIdx.x * 64 + pid * 32;
    const int g    = l >> 2;
    const int q2   = (l & 3) * 2;

    float*    w21sp = (float*)smbuf + pid * 2304;               // [64][36]
    uint32_t* w12ps = (uint32_t*)(smbuf + 18432) + pid * 1024;  // 32 words x 32 lanes
    float*    Cs    = (float*)(smbuf + 26624);                  // 4 tiles x 1024 f

    uint32_t w12p[2][16];

    if (role == 0) {
        // ---------- C1 = relu(cat@W11+b11); W12f = C1@W12+b12; pack ----------
        #pragma unroll
        for (int ti = 0; ti < 2; ti++) {
            const int gra = pairBase + ti * 16 + g;
            const int grb = gra + 8;

            float C1[8][4];
            #pragma unroll
            for (int nt = 0; nt < 8; nt++)
                #pragma unroll
                for (int k = 0; k < 4; k++) C1[nt][k] = 0.f;

            #pragma unroll
            for (int kc = 0; kc < 8; kc++) {
                const int i0 = kc * 16 + q2;
                float2 p0 = catld(img, loc, gra, i0);
                float2 p1 = catld(img, loc, grb, i0);
                float2 p2 = catld(img, loc, gra, i0 + 8);
                float2 p3 = catld(img, loc, grb, i0 + 8);
                uint32_t ah[4], al[4];
                split_pair(p0.x, p0.y, ah[0], al[0]);
                split_pair(p1.x, p1.y, ah[1], al[1]);
                split_pair(p2.x, p2.y, ah[2], al[2]);
                split_pair(p3.x, p3.y, ah[3], al[3]);
                #pragma unroll
                for (int nt = 0; nt < 8; nt++) {
                    const uint8_t* p = g_W11pk + (kc * 8 + nt) * 256 + l * 8;
                    uint2 bh = __ldg((const uint2*)p);
                    uint2 bl = __ldg((const uint2*)(p + 16384));
                    MMA_BF16(C1[nt], ah, bh.x, bh.y);
                    MMA_BF16(C1[nt], ah, bl.x, bl.y);
                    MMA_BF16(C1[nt], al, bh.x, bh.y);
                }
            }
            #pragma unroll
            for (int nt = 0; nt < 8; nt++) {
                int col = nt * 8 + q2;
                float u0 = __ldg(b11 + col), u1 = __ldg(b11 + col + 1);
                C1[nt][0] = fmaxf(C1[nt][0] + u0, 0.f);
                C1[nt][1] = fmaxf(C1[nt][1] + u1, 0.f);
                C1[nt][2] = fmaxf(C1[nt][2] + u0, 0.f);
                C1[nt][3] = fmaxf(C1[nt][3] + u1, 0.f);
            }

            float Wf[8][4];
            #pragma unroll
            for (int nt = 0; nt < 8; nt++)
                #pragma unroll
                for (int k = 0; k < 4; k++) Wf[nt][k] = 0.f;

            #pragma unroll
            for (int kc = 0; kc < 4; kc++) {
                uint32_t ah[4], al[4];
                split_pair(C1[2*kc][0],   C1[2*kc][1],   ah[0], al[0]);
                split_pair(C1[2*kc][2],   C1[2*kc][3],   ah[1], al[1]);
                split_pair(C1[2*kc+1][0], C1[2*kc+1][1], ah[2], al[2]);
                split_pair(C1[2*kc+1][2], C1[2*kc+1][3], ah[3], al[3]);
                #pragma unroll
                for (int nt = 0; nt < 8; nt++) {
                    const uint8_t* p = g_W12pk + (kc * 8 + nt) * 256 + l * 8;
                    uint2 bh = __ldg((const uint2*)p);
                    uint2 bl = __ldg((const uint2*)(p + 8192));
                    MMA_BF16(Wf[nt], ah, bh.x, bh.y);
                    MMA_BF16(Wf[nt], ah, bl.x, bl.y);
                    MMA_BF16(Wf[nt], al, bh.x, bh.y);
                }
            }
            #pragma unroll
            for (int kc = 0; kc < 4; kc++) {
                int c0 = (2*kc) * 8 + q2, c1 = (2*kc+1) * 8 + q2;
                float e00 = __ldg(b12 + c0), e01 = __ldg(b12 + c0 + 1);
                float e10 = __ldg(b12 + c1), e11 = __ldg(b12 + c1 + 1);
                w12p[ti][kc*4+0] = f16x2(Wf[2*kc][0] + e00,   Wf[2*kc][1] + e01);
                w12p[ti][kc*4+1] = f16x2(Wf[2*kc][2] + e00,   Wf[2*kc][3] + e01);
                w12p[ti][kc*4+2] = f16x2(Wf[2*kc+1][0] + e10, Wf[2*kc+1][1] + e11);
                w12p[ti][kc*4+3] = f16x2(Wf[2*kc+1][2] + e10, Wf[2*kc+1][3] + e11);
            }
        }
        // share w12 fragments (identical lane layout in partner warp)
        #pragma unroll
        for (int ti = 0; ti < 2; ti++)
            #pragma unroll
            for (int i = 0; i < 16; i++)
                w12ps[(ti * 16 + i) * 32 + l] = w12p[ti][i];
    } else {
        // ---------- C2 = relu(cat@W21+b21) -> w21sp (all 64 rows) ----------
        #pragma unroll
        for (int ti = 0; ti < 2; ti++) {
            const int gra = pairBase + ti * 16 + g;
            const int grb = gra + 8;
            const int ra  = ti * 16 + g, rb = ra + 8;   // local token ids

            float C2[8][4];
            #pragma unroll
            for (int nt = 0; nt < 8; nt++)
                #pragma unroll
                for (int k = 0; k < 4; k++) C2[nt][k] = 0.f;

            #pragma unroll
            for (int kc = 0; kc < 8; kc++) {
                const int i0 = kc * 16 + q2;
                float2 p0 = catld(img, loc, gra, i0);
                float2 p1 = catld(img, loc, grb, i0);
                float2 p2 = catld(img, loc, gra, i0 + 8);
                float2 p3 = catld(img, loc, grb, i0 + 8);
                uint32_t ah[4], al[4];
                split_pair(p0.x, p0.y, ah[0], al[0]);
                split_pair(p1.x, p1.y, ah[1], al[1]);
                split_pair(p2.x, p2.y, ah[2], al[2]);
                split_pair(p3.x, p3.y, ah[3], al[3]);
                #pragma unroll
                for (int nt = 0; nt < 8; nt++) {
                    const uint8_t* p = g_W21pk + (kc * 8 + nt) * 256 + l * 8;
                    uint2 bh = __ldg((const uint2*)p);
                    uint2 bl = __ldg((const uint2*)(p + 16384));
                    MMA_BF16(C2[nt], ah, bh.x, bh.y);
                    MMA_BF16(C2[nt], ah, bl.x, bl.y);
                    MMA_BF16(C2[nt], al, bh.x, bh.y);
                }
            }
            #pragma unroll
            for (int nt = 0; nt < 8; nt++) {
                int col = nt * 8 + q2;
                float v0 = __ldg(b21 + col), v1 = __ldg(b21 + col + 1);
                w21sp[(col    ) * 36 + ra] = fmaxf(C2[nt][0] + v0, 0.f);
                w21sp[(col + 1) * 36 + ra] = fmaxf(C2[nt][1] + v1, 0.f);
                w21sp[(col    ) * 36 + rb] = fmaxf(C2[nt][2] + v0, 0.f);
                w21sp[(col + 1) * 36 + rb] = fmaxf(C2[nt][3] + v1, 0.f);
            }
        }
    }
    __syncthreads();
    if (role == 1) {
        #pragma unroll
        for (int ti = 0; ti < 2; ti++)
            #pragma unroll
            for (int i = 0; i < 16; i++)
                w12p[ti][i] = w12ps[(ti * 16 + i) * 32 + l];
    }

    // ================= main bilinear GEMM: this warp's j-range ==============
    float C[2][8][4];
    #pragma unroll
    for (int ti = 0; ti < 2; ti++)
        #pragma unroll
        for (int nt = 0; nt < 8; nt++)
            #pragma unroll
            for (int k = 0; k < 4; k++) C[ti][nt][k] = 0.f;

    const int nj    = 32 + role;     // role1 also covers the j=64 bias chunk
    const int jbase = role * 32;

    for (int jj = 0; jj < nj; jj++) {
        const int j = jbase + jj;
        float v0a = 1.f, v0b = 1.f, v1a = 1.f, v1b = 1.f;
        if (j < 64) {
            const float* r = w21sp + j * 36;
            v0a = r[g]; v0b = r[g + 8]; v1a = r[g + 16]; v1b = r[g + 24];
        }
        uint32_t h0a = f16x2(v0a, v0a), h0b = f16x2(v0b, v0b);
        uint32_t h1a = f16x2(v1a, v1a), h1b = f16x2(v1b, v1b);
        const uint8_t* panel = g_BpkH + j * 8192 + l * 16;

        #pragma unroll
        for (int kc = 0; kc < 4; kc++) {
            uint4 bb0 = __ldg((const uint4*)(panel + (kc * 4 + 0) * 512));
            uint4 bb1 = __ldg((const uint4*)(panel + (kc * 4 + 1) * 512));
            uint4 bb2 = __ldg((const uint4*)(panel + (kc * 4 + 2) * 512));
            uint4 bb3 = __ldg((const uint4*)(panel + (kc * 4 + 3) * 512));
            uint32_t A0[4], A1[4];
            A0[0] = hmul2(h0a, w12p[0][kc*4+0]);
            A0[1] = hmul2(h0b, w12p[0][kc*4+1]);
            A0[2] = hmul2(h0a, w12p[0][kc*4+2]);
            A0[3] = hmul2(h0b, w12p[0][kc*4+3]);
            A1[0] = hmul2(h1a, w12p[1][kc*4+0]);
            A1[1] = hmul2(h1b, w12p[1][kc*4+1]);
            A1[2] = hmul2(h1a, w12p[1][kc*4+2]);
            A1[3] = hmul2(h1b, w12p[1][kc*4+3]);
            MMA_F16(C[0][0], A0, bb0.x, bb0.y);
            MMA_F16(C[0][1], A0, bb0.z, bb0.w);
            MMA_F16(C[0][2], A0, bb1.x, bb1.y);
            MMA_F16(C[0][3], A0, bb1.z, bb1.w);
            MMA_F16(C[0][4], A0, bb2.x, bb2.y);
            MMA_F16(C[0][5], A0, bb2.z, bb2.w);
            MMA_F16(C[0][6], A0, bb3.x, bb3.y);
            MMA_F16(C[0][7], A0, bb3.z, bb3.w);
            MMA_F16(C[1][0], A1, bb0.x, bb0.y);
            MMA_F16(C[1][1], A1, bb0.z, bb0.w);
            MMA_F16(C[1][2], A1, bb1.x, bb1.y);
            MMA_F16(C[1][3], A1, bb1.z, bb1.w);
            MMA_F16(C[1][4], A1, bb2.x, bb2.y);
            MMA_F16(C[1][5], A1, bb2.z, bb2.w);
            MMA_F16(C[1][6], A1, bb3.x, bb3.y);
            MMA_F16(C[1][7], A1, bb3.z, bb3.w);
        }
    }

    // ================= combine partial C across the pair ====================
    {
        float* dst = Cs + (pid * 2 + (role ^ 1)) * 1024;
        #pragma unroll
        for (int nt = 0; nt < 8; nt++)
            #pragma unroll
            for (int k = 0; k < 4; k++)
                dst[(nt * 4 + k) * 32 + l] = C[role ^ 1][nt][k];
    }
    __syncthreads();

    float Ct[8][4];
    {
        const float* src = Cs + (pid * 2 + role) * 1024;
        #pragma unroll
        for (int nt = 0; nt < 8; nt++)
            #pragma unroll
            for (int k = 0; k < 4; k++)
                Ct[nt][k] = C[role][nt][k] + src[(nt * 4 + k) * 32 + l];
    }

    // ================= LN + ReLU + y@W3 + b3 for tile = role ===============
    {
        float sa = 0.f, sb2 = 0.f;
        #pragma unroll
        for (int nt = 0; nt < 8; nt++) { sa += Ct[nt][0] + Ct[nt][1]; sb2 += Ct[nt][2] + Ct[nt][3]; }
        sa  += __shfl_xor_sync(0xffffffffu, sa, 1);
        sa  += __shfl_xor_sync(0xffffffffu, sa, 2);
        sb2 += __shfl_xor_sync(0xffffffffu, sb2, 1);
        sb2 += __shfl_xor_sync(0xffffffffu, sb2, 2);
        float mua = sa * (1.0f / 64.0f), mub = sb2 * (1.0f / 64.0f);
        float qa = 0.f, qb = 0.f;
        #pragma unroll
        for (int nt = 0; nt < 8; nt++) {
            Ct[nt][0] -= mua; Ct[nt][1] -= mua; Ct[nt][2] -= mub; Ct[nt][3] -= mub;
            qa = fmaf(Ct[nt][0], Ct[nt][0], qa); qa = fmaf(Ct[nt][1], Ct[nt][1], qa);
            qb = fmaf(Ct[nt][2], Ct[nt][2], qb); qb = fmaf(Ct[nt][3], Ct[nt][3], qb);
        }
        qa += __shfl_xor_sync(0xffffffffu, qa, 1);
        qa += __shfl_xor_sync(0xffffffffu, qa, 2);
        qb += __shfl_xor_sync(0xffffffffu, qb, 1);
        qb += __shfl_xor_sync(0xffffffffu, qb, 2);
        float rsa = rsqrtf(qa * (1.0f / 64.0f) + 1e-5f);
        float rsb = rsqrtf(qb * (1.0f / 64.0f) + 1e-5f);
        #pragma unroll
        for (int nt = 0; nt < 8; nt++) {
            int col = nt * 8 + q2;
            float g0 = __ldg(lnG + col), g1 = __ldg(lnG + col + 1);
            float e0 = __ldg(lnB + col), e1 = __ldg(lnB + col + 1);
            Ct[nt][0] = fmaxf(fmaf(Ct[nt][0] * rsa, g0, e0), 0.f);
            Ct[nt][1] = fmaxf(fmaf(Ct[nt][1] * rsa, g1, e1), 0.f);
            Ct[nt][2] = fmaxf(fmaf(Ct[nt][2] * rsb, g0, e0), 0.f);
            Ct[nt][3] = fmaxf(fmaf(Ct[nt][3] * rsb, g1, e1), 0.f);
        }
    }
    {
        float D[8][4];
        #pragma unroll
        for (int nt = 0; nt < 8; nt++)
            #pragma unroll
            for (int k = 0; k < 4; k++) D[nt][k] = 0.f;

        #pragma unroll
        for (int kc = 0; kc < 4; kc++) {
            uint32_t A[4];
            A[0] = f16x2(Ct[2*kc][0],   Ct[2*kc][1]);
            A[1] = f16x2(Ct[2*kc][2],   Ct[2*kc][3]);
            A[2] = f16x2(Ct[2*kc+1][0], Ct[2*kc+1][1]);
            A[3] = f16x2(Ct[2*kc+1][2], Ct[2*kc+1][3]);
            const uint8_t* panel = g_W3pkH + l * 16;
            uint4 bb0 = __ldg((const uint4*)(panel + (kc * 4 + 0) * 512));
            uint4 bb1 = __ldg((const uint4*)(panel + (kc * 4 + 1) * 512));
            uint4 bb2 = __ldg((const uint4*)(panel + (kc * 4 + 2) * 512));
            uint4 bb3 = __ldg((const uint4*)(panel + (kc * 4 + 3) * 512));
            MMA_F16(D[0], A, bb0.x, bb0.y);
            MMA_F16(D[1], A, bb0.z, bb0.w);
            MMA_F16(D[2], A, bb1.x, bb1.y);
            MMA_F16(D[3], A, bb1.z, bb1.w);
            MMA_F16(D[4], A, bb2.x, bb2.y);
            MMA_F16(D[5], A, bb2.z, bb2.w);
            MMA_F16(D[6], A, bb3.x, bb3.y);
            MMA_F16(D[7], A, bb3.z, bb3.w);
        }

        const int gra = pairBase + role * 16 + g;
        float* outA = out + gra * 64;
        float* outB = out + (gra + 8) * 64;
        #pragma unroll
        for (int nt = 0; nt < 8; nt++) {
            int col = nt * 8 + q2;
            float b30 = __ldg(b3 + col), b31 = __ldg(b3 + col + 1);
            *(float2*)(outA + col) = make_float2(D[nt][0] + b30, D[nt][1] + b31);
            *(float2*)(outB + col) = make_float2(D[nt][2] + b30, D[nt][3] + b31);
        }
    }
}

// ---------------------------------------------------------------------------
extern "C" void kernel_launch(void* const* d_in, const int* in_sizes, int n_in,
                              void* d_out, int out_size)
{
    const float* img = (const float*)d_in[0];
    const float* loc = (const float*)d_in[1];
    const float* W11 = (const float*)d_in[2];
    const float* b11 = (const float*)d_in[3];
    const float* W12 = (const float*)d_in[4];
    const float* b12 = (const float*)d_in[5];
    const float* W21 = (const float*)d_in[6];
    const float* b21 = (const float*)d_in[7];
    const float* W22 = (const float*)d_in[8];
    const float* b22 = (const float*)d_in[9];
    const float* lnG = (const float*)d_in[10];
    const float* lnB = (const float*)d_in[11];
    const float* W3  = (const float*)d_in[12];
    const float* b3  = (const float*)d_in[13];
    float* out = (float*)d_out;

    cudaFuncSetAttribute(fused_kernel, cudaFuncAttributeMaxDynamicSharedMemorySize, (int)S_SZ);

    convert_kernel<<<152, 256>>>(W22, b22, W3, W11, W21, W12);
    fused_kernel<<<NCTA, 128, S_SZ>>>(img, loc, b11, b21, b12, lnG, lnB, b3, out);
}